// round 8
// baseline (speedup 1.0000x reference)
#include <cuda_runtime.h>
#include <cuda_fp16.h>
#include <cstdint>

// QLSTM: T=512, B=256, D=128, H=256, P=128. GAMMA=1.
// 128 persistent CTAs; each CTA = two independent 512-thread halves
// (one batch row each) pipelined against each other via named barriers.
// R7: split-half pipelining + x prefetch + fused epilogue.

#define T_STEPS 512
#define BATCH   256
#define DIN     128
#define HID     256
#define PROTO   128
#define DH      384
#define QP      96           // uint2 (4-dim) groups per proto row
#define GATES4  1024
#define BC      2
#define NCTA    (BATCH / BC)
#define NTHREADS 1024
#define HALF_T  512
#define PS      32           // p-rows of W resident in SMEM

__device__ uint2  g_protoP2[QP * PROTO];     // [q][p]: 2x half2 = dims 4q..4q+3
__device__ float  g_pnorm[PROTO];
__device__ __half g_WallT[PROTO * GATES4];   // [p][j], j = gate*256 + h

__global__ void prep_kernel(const float* __restrict__ proto,
                            const float* __restrict__ Wf, const float* __restrict__ Wi,
                            const float* __restrict__ Wg, const float* __restrict__ Wo) {
    int tid = blockIdx.x * blockDim.x + threadIdx.x;
    int nth = gridDim.x * blockDim.x;
    for (int idx = tid; idx < PROTO * GATES4; idx += nth) {
        int p = idx >> 10;
        int j = idx & 1023;
        int g = j >> 8;
        int h = j & 255;
        const float* W = (g == 0) ? Wf : (g == 1) ? Wi : (g == 2) ? Wg : Wo;
        g_WallT[idx] = __float2half(W[h * PROTO + p]);
    }
    for (int idx = tid; idx < QP * PROTO; idx += nth) {
        int p = idx & (PROTO - 1);
        int q = idx >> 7;
        __half2 a = __floats2half2_rn(proto[p * DH + 4 * q],     proto[p * DH + 4 * q + 1]);
        __half2 b = __floats2half2_rn(proto[p * DH + 4 * q + 2], proto[p * DH + 4 * q + 3]);
        uint2 v;
        v.x = *reinterpret_cast<unsigned int*>(&a);
        v.y = *reinterpret_cast<unsigned int*>(&b);
        g_protoP2[idx] = v;
    }
    for (int p = tid; p < PROTO; p += nth) {
        float s = 0.f;
        for (int d = 0; d < DH; d++) { float v = proto[p * DH + d]; s += v * v; }
        g_pnorm[p] = s;
    }
}

struct Smem {
    uint2   protoP2[QP * PROTO];      // 98304 B (shared read-only)
    __half  Wsm[PS * GATES4];         // 65536 B (shared read-only)
    float   part1[BC][4][PROTO];      // 4096 B  (per-half)
    float   part2[BC][2][GATES4];     // 16384 B (per-half)
    float   comb[BC][DH];             // 3072 B  fp32 (cnorm source)
    __half  combh[BC][DH];            // 1536 B  fp16 mirror (phase-1 operand)
    float   csm[BC][HID];             // 2048 B
    __half2 kh[BC][PROTO];            // 1024 B  (k,k)
    float   bsm[GATES4];              // 4096 B
    float   pnorm[PROTO];             // 512 B
    float   cn[BC];                   // 8 B
};                                    // ~192 KB

__device__ __forceinline__ float fast_sigmoid(float z) {
    return __fdividef(1.0f, 1.0f + __expf(-z));
}
__device__ __forceinline__ float fast_tanh(float z) {
    float r;
    asm("tanh.approx.f32 %0, %1;" : "=f"(r) : "f"(z));
    return r;
}
__device__ __forceinline__ __half2 u2h(unsigned int v) {
    return *reinterpret_cast<__half2*>(&v);
}

__global__ __launch_bounds__(NTHREADS, 1)
void qlstm_kernel(const float* __restrict__ x,
                  const float* __restrict__ bf, const float* __restrict__ bi,
                  const float* __restrict__ bg, const float* __restrict__ bo,
                  float* __restrict__ out) {
    extern __shared__ char smem_raw[];
    Smem& s = *reinterpret_cast<Smem*>(smem_raw);

    const int t    = threadIdx.x;
    const int cta  = blockIdx.x;
    const int half = t >> 9;          // 0/1 = batch row within CTA
    const int ht   = t & 511;         // thread within half
    const int lane = t & 31;
    const int hwid = ht >> 5;         // warp within half (0..15)
    const int barid = 1 + half;

    // ---- one-time CTA init (all 1024 threads) ----
    {
        for (int i = t; i < QP * PROTO; i += NTHREADS) s.protoP2[i] = g_protoP2[i];
        const unsigned int* wsrc = reinterpret_cast<const unsigned int*>(g_WallT);
        unsigned int*       wdst = reinterpret_cast<unsigned int*>(s.Wsm);
        for (int i = t; i < PS * GATES4 / 2; i += NTHREADS) wdst[i] = wsrc[i];
        for (int i = t; i < PROTO; i += NTHREADS) s.pnorm[i] = g_pnorm[i];
        for (int i = t; i < GATES4; i += NTHREADS) {
            int g = i >> 8, h = i & 255;
            const float* bb = (g == 0) ? bf : (g == 1) ? bi : (g == 2) ? bg : bo;
            s.bsm[i] = bb[h];
        }
        for (int i = t; i < BC * HID; i += NTHREADS) {
            int b = i >> 8, h = i & 255;
            s.comb[b][DIN + h]  = 0.f;
            s.combh[b][DIN + h] = __float2half(0.f);
            s.csm[b][h]         = 0.f;
        }
    }
    __syncthreads();   // only full-CTA barrier; halves are independent after this

    // per-half mappings
    const int chunk = ht >> 7;        // phase 1: 0..3, 96 dims each
    const int pp    = ht & 127;
    const int pg    = ht >> 8;        // phase 2: 0..1, 64 p each
    const int jq    = ht & 255;       // col quad
    const int j0    = jq * 4;
    const int bgl   = cta * BC + half;

    #define HBAR() asm volatile("bar.sync %0, %1;" :: "r"(barid), "r"(HALF_T) : "memory")

    // prefetch x for step 0
    float2 xr = make_float2(0.f, 0.f);
    if (ht < 64)
        xr = reinterpret_cast<const float2*>(x + (size_t)bgl * DIN)[ht];

    for (int step = 0; step < T_STEPS; step++) {
        // ---- phase 0: commit prefetched x_t ----
        if (ht < 64) {
            reinterpret_cast<float2*>(&s.comb[half][0])[ht] = xr;
            reinterpret_cast<__half2*>(&s.combh[half][0])[ht] =
                __floats2half2_rn(xr.x, xr.y);
        }
        HBAR();   // B1: x + h(prev) visible

        // prefetch x for step+1 (latency hidden across this whole step)
        if (ht < 64 && step + 1 < T_STEPS)
            xr = reinterpret_cast<const float2*>(
                     x + ((size_t)(step + 1) * BATCH + bgl) * DIN)[ht];

        // ---- cnorm (warp 0 of each half, fp32) ----
        if (hwid == 0) {
            float cn = 0.f;
            const float* cb = s.comb[half];
            #pragma unroll
            for (int i = 0; i < 12; i++) { float v = cb[lane * 12 + i]; cn = fmaf(v, v, cn); }
            #pragma unroll
            for (int o = 16; o; o >>= 1) cn += __shfl_xor_sync(0xffffffffu, cn, o);
            if (lane == 0) s.cn[half] = cn;
        }

        // ---- phase 1 partial: 96 dims per thread, HFMA2, 2 accums ----
        {
            __half2 accA = __float2half2_rn(0.f);
            __half2 accB = __float2half2_rn(0.f);
            const uint4* cb = reinterpret_cast<const uint4*>(&s.combh[half][0]) + chunk * 12;
            const uint2* pr = s.protoP2 + (chunk * 24) * PROTO + pp;
            #pragma unroll
            for (int i = 0; i < 12; i += 2) {
                uint4 c0 = cb[i];
                uint2 w0 = pr[(2 * i) * PROTO];
                uint2 w1 = pr[(2 * i + 1) * PROTO];
                accA = __hfma2(u2h(c0.x), u2h(w0.x), accA);
                accA = __hfma2(u2h(c0.y), u2h(w0.y), accA);
                accA = __hfma2(u2h(c0.z), u2h(w1.x), accA);
                accA = __hfma2(u2h(c0.w), u2h(w1.y), accA);
                uint4 c1 = cb[i + 1];
                uint2 w2 = pr[(2 * i + 2) * PROTO];
                uint2 w3 = pr[(2 * i + 3) * PROTO];
                accB = __hfma2(u2h(c1.x), u2h(w2.x), accB);
                accB = __hfma2(u2h(c1.y), u2h(w2.y), accB);
                accB = __hfma2(u2h(c1.z), u2h(w3.x), accB);
                accB = __hfma2(u2h(c1.w), u2h(w3.y), accB);
            }
            float2 fA = __half22float2(accA);
            float2 fB = __half22float2(accB);
            s.part1[half][chunk][pp] = (fA.x + fA.y) + (fB.x + fB.y);
        }
        HBAR();   // B2

        // ---- phase 1 combine: k = exp(2*dot - cnorm - pnorm) ----
        if (ht < PROTO) {
            float d = s.part1[half][0][ht] + s.part1[half][1][ht]
                    + s.part1[half][2][ht] + s.part1[half][3][ht];
            float k = __expf(2.f * d - s.cn[half] - s.pnorm[ht]);
            s.kh[half][ht] = __float2half2_rn(k);
        }
        HBAR();   // B3

        // ---- phase 2 partial: 4 cols x 64 p per thread (two 32-p fp16 chains) ----
        {
            __half2 a01 = __float2half2_rn(0.f), a23 = a01;
            __half2 b01 = a01, b23 = a01;
            const __half2* kp = &s.kh[half][pg * 64];
            if (pg == 0) {
                const uint2* ws = reinterpret_cast<const uint2*>(s.Wsm) + jq;
                #pragma unroll 8
                for (int i = 0; i < 32; i++) {
                    uint2 w = ws[i * 256];
                    __half2 k = kp[i];
                    a01 = __hfma2(k, u2h(w.x), a01);
                    a23 = __hfma2(k, u2h(w.y), a23);
                }
                const uint2* wg = reinterpret_cast<const uint2*>(g_WallT) + jq;
                #pragma unroll 8
                for (int i = 32; i < 64; i++) {
                    uint2 w = wg[(size_t)i * 256];
                    __half2 k = kp[i];
                    b01 = __hfma2(k, u2h(w.x), b01);
                    b23 = __hfma2(k, u2h(w.y), b23);
                }
            } else {
                const uint2* wg = reinterpret_cast<const uint2*>(g_WallT) + jq;
                #pragma unroll 8
                for (int i = 0; i < 32; i++) {
                    uint2 w = wg[(size_t)(64 + i) * 256];
                    __half2 k = kp[i];
                    a01 = __hfma2(k, u2h(w.x), a01);
                    a23 = __hfma2(k, u2h(w.y), a23);
                }
                #pragma unroll 8
                for (int i = 32; i < 64; i++) {
                    uint2 w = wg[(size_t)(64 + i) * 256];
                    __half2 k = kp[i];
                    b01 = __hfma2(k, u2h(w.x), b01);
                    b23 = __hfma2(k, u2h(w.y), b23);
                }
            }
            float2 ra = __half22float2(a01), rb = __half22float2(b01);
            float2 rc = __half22float2(a23), rd = __half22float2(b23);
            *reinterpret_cast<float4*>(&s.part2[half][pg][j0]) =
                make_float4(ra.x + rb.x, ra.y + rb.y, rc.x + rd.x, rc.y + rd.y);
        }
        HBAR();   // B4

        // ---- fused epilogue: gate sums + activations + cell update + output ----
        if (ht < HID) {
            int h = ht;
            float zf = s.part2[half][0][h]       + s.part2[half][1][h]       + s.bsm[h];
            float zi = s.part2[half][0][256 + h] + s.part2[half][1][256 + h] + s.bsm[256 + h];
            float zg = s.part2[half][0][512 + h] + s.part2[half][1][512 + h] + s.bsm[512 + h];
            float zo = s.part2[half][0][768 + h] + s.part2[half][1][768 + h] + s.bsm[768 + h];
            float fg = fast_sigmoid(zf);
            float ig = fast_sigmoid(zi);
            float gg = fast_tanh(zg);
            float og = fast_sigmoid(zo);
            float c  = fmaf(fg, s.csm[half][h], ig * gg);
            s.csm[half][h] = c;
            float hn = og * fast_tanh(c);
            s.comb[half][DIN + h]  = hn;
            s.combh[half][DIN + h] = __float2half(hn);
            out[(size_t)step * BATCH * HID + (size_t)bgl * HID + h] = hn;
            if (step == T_STEPS - 1) {
                size_t base = (size_t)T_STEPS * BATCH * HID;
                out[base + (size_t)bgl * HID + h]                       = hn;
                out[base + (size_t)BATCH * HID + (size_t)bgl * HID + h] = c;
            }
        }
        // wraparound: B1 of next step orders epilogue writes before phase-1 reads
    }
    #undef HBAR
}

extern "C" void kernel_launch(void* const* d_in, const int* in_sizes, int n_in,
                              void* d_out, int out_size) {
    const float* x     = (const float*)d_in[0];
    const float* proto = (const float*)d_in[1];
    const float* Wf    = (const float*)d_in[2];
    const float* bf    = (const float*)d_in[3];
    const float* Wi    = (const float*)d_in[4];
    const float* bi    = (const float*)d_in[5];
    const float* Wg    = (const float*)d_in[6];
    const float* bg    = (const float*)d_in[7];
    const float* Wo    = (const float*)d_in[8];
    const float* bo    = (const float*)d_in[9];
    float* out = (float*)d_out;

    cudaFuncSetAttribute(qlstm_kernel, cudaFuncAttributeMaxDynamicSharedMemorySize,
                         (int)sizeof(Smem));

    prep_kernel<<<128, 256>>>(proto, Wf, Wi, Wg, Wo);
    qlstm_kernel<<<NCTA, NTHREADS, sizeof(Smem)>>>(x, bf, bi, bg, bo, out);
}

// round 10
// speedup vs baseline: 1.0630x; 1.0630x over previous
#include <cuda_runtime.h>
#include <cuda_fp16.h>
#include <cstdint>

// QLSTM: T=512, B=256, D=128, H=256, P=128. GAMMA=1.
// 128 persistent CTAs x 2 coupled batch rows (shared proto/W reads), 1024 threads.
// R9: R7 topology + uint4 loads, packed-k broadcast, fused epilogue, 4 barriers.

#define T_STEPS 512
#define BATCH   256
#define DIN     128
#define HID     256
#define PROTO   128
#define DH      384
#define Q4      48           // uint4 (8-dim) groups per proto row
#define GATES4  1024
#define BC      2
#define NCTA    (BATCH / BC)
#define NTHREADS 1024
#define PSROWS  16           // p-rows of W resident in SMEM
#define NPG     8            // phase-2 p-groups
#define PPG     16           // p per group

__device__ uint4  g_protoP4[Q4 * PROTO];     // [q4][p]: 4x half2 = dims 8q4..8q4+7
__device__ float  g_pnorm[PROTO];
__device__ __half g_WallT[PROTO * GATES4];   // [p][j], j = gate*256 + h

__global__ void prep_kernel(const float* __restrict__ proto,
                            const float* __restrict__ Wf, const float* __restrict__ Wi,
                            const float* __restrict__ Wg, const float* __restrict__ Wo) {
    int tid = blockIdx.x * blockDim.x + threadIdx.x;
    int nth = gridDim.x * blockDim.x;
    for (int idx = tid; idx < PROTO * GATES4; idx += nth) {
        int p = idx >> 10;
        int j = idx & 1023;
        int g = j >> 8;
        int h = j & 255;
        const float* W = (g == 0) ? Wf : (g == 1) ? Wi : (g == 2) ? Wg : Wo;
        g_WallT[idx] = __float2half(W[h * PROTO + p]);
    }
    for (int idx = tid; idx < Q4 * PROTO; idx += nth) {
        int p = idx & (PROTO - 1);
        int q = idx >> 7;
        __half2 a = __floats2half2_rn(proto[p * DH + 8 * q],     proto[p * DH + 8 * q + 1]);
        __half2 b = __floats2half2_rn(proto[p * DH + 8 * q + 2], proto[p * DH + 8 * q + 3]);
        __half2 c = __floats2half2_rn(proto[p * DH + 8 * q + 4], proto[p * DH + 8 * q + 5]);
        __half2 d = __floats2half2_rn(proto[p * DH + 8 * q + 6], proto[p * DH + 8 * q + 7]);
        uint4 v;
        v.x = *reinterpret_cast<unsigned int*>(&a);
        v.y = *reinterpret_cast<unsigned int*>(&b);
        v.z = *reinterpret_cast<unsigned int*>(&c);
        v.w = *reinterpret_cast<unsigned int*>(&d);
        g_protoP4[idx] = v;
    }
    for (int p = tid; p < PROTO; p += nth) {
        float s = 0.f;
        for (int d = 0; d < DH; d++) { float v = proto[p * DH + d]; s += v * v; }
        g_pnorm[p] = s;
    }
}

struct Smem {
    uint4   protoP4[Q4 * PROTO];      // 98304 B
    __half  Wsm[PSROWS * GATES4];     // 32768 B  (p-rows 0..15)
    float   part1[8][2][PROTO];       // 8192 B   (chunk, row, p)
    float2  part2[NPG][GATES4];       // 65536 B  (pg, col) -> (row0, row1)
    float   comb[BC][DH];             // 3072 B
    __half  combh[BC][DH];            // 1536 B
    float   csm[BC][HID];             // 2048 B
    __half2 kh[PROTO];                // 512 B    (k_row0, k_row1)
    float   bsm[GATES4];              // 4096 B
    float   pnorm[PROTO];             // 512 B
    float   cn[BC];                   // 8 B
};                                    // ~216.5 KB

__device__ __forceinline__ float fast_sigmoid(float z) {
    return __fdividef(1.0f, 1.0f + __expf(-z));
}
__device__ __forceinline__ float fast_tanh(float z) {
    float r;
    asm("tanh.approx.f32 %0, %1;" : "=f"(r) : "f"(z));
    return r;
}
__device__ __forceinline__ __half2 u2h(unsigned int v) {
    return *reinterpret_cast<__half2*>(&v);
}

__global__ __launch_bounds__(NTHREADS, 1)
void qlstm_kernel(const float* __restrict__ x,
                  const float* __restrict__ bf, const float* __restrict__ bi,
                  const float* __restrict__ bg, const float* __restrict__ bo,
                  float* __restrict__ out) {
    extern __shared__ char smem_raw[];
    Smem& s = *reinterpret_cast<Smem*>(smem_raw);

    const int t    = threadIdx.x;
    const int cta  = blockIdx.x;
    const int wid  = t >> 5;
    const int lane = t & 31;

    // ---- one-time CTA init ----
    {
        for (int i = t; i < Q4 * PROTO; i += NTHREADS) s.protoP4[i] = g_protoP4[i];
        const uint4* wsrc = reinterpret_cast<const uint4*>(g_WallT);
        uint4*       wdst = reinterpret_cast<uint4*>(s.Wsm);
        for (int i = t; i < PSROWS * GATES4 / 8; i += NTHREADS) wdst[i] = wsrc[i];
        for (int i = t; i < PROTO; i += NTHREADS) s.pnorm[i] = g_pnorm[i];
        for (int i = t; i < GATES4; i += NTHREADS) {
            int g = i >> 8, h = i & 255;
            const float* bb = (g == 0) ? bf : (g == 1) ? bi : (g == 2) ? bg : bo;
            s.bsm[i] = bb[h];
        }
        for (int i = t; i < BC * HID; i += NTHREADS) {
            int b = i >> 8, h = i & 255;
            s.comb[b][DIN + h]  = 0.f;
            s.combh[b][DIN + h] = __float2half(0.f);
            s.csm[b][h]         = 0.f;
        }
    }
    __syncthreads();

    // phase-1 mapping: 8 chunks x 128 protos; chunk = 48 dims = 6 uint4
    const int chunk = t >> 7;
    const int pp    = t & 127;
    // phase-2 mapping: 8 p-groups x 128 col-octets
    const int pg    = t >> 7;
    const int jo    = t & 127;
    const int j0    = jo * 8;

    // prefetch x for step 0 (t<128: b = t>>6, pair index t&63)
    float2 xr = make_float2(0.f, 0.f);
    if (t < 128)
        xr = reinterpret_cast<const float2*>(
                 x + (size_t)(cta * BC + (t >> 6)) * DIN)[t & 63];

    for (int step = 0; step < T_STEPS; step++) {
        // ---- phase 0: commit prefetched x_t ----
        if (t < 128) {
            int b = t >> 6, i2 = t & 63;
            reinterpret_cast<float2*>(&s.comb[b][0])[i2] = xr;
            reinterpret_cast<__half2*>(&s.combh[b][0])[i2] = __floats2half2_rn(xr.x, xr.y);
        }
        __syncthreads();   // S0

        // prefetch x for step+1
        if (t < 128 && step + 1 < T_STEPS)
            xr = reinterpret_cast<const float2*>(
                     x + ((size_t)(step + 1) * BATCH + cta * BC + (t >> 6)) * DIN)[t & 63];

        // ---- cnorm (warps 0,1; fp32) ----
        if (wid < 2) {
            float cn = 0.f;
            const float* cb = s.comb[wid];
            #pragma unroll
            for (int i = 0; i < 12; i++) { float v = cb[lane * 12 + i]; cn = fmaf(v, v, cn); }
            #pragma unroll
            for (int o = 16; o; o >>= 1) cn += __shfl_xor_sync(0xffffffffu, cn, o);
            if (lane == 0) s.cn[wid] = cn;
        }

        // ---- phase 1 partial: 48 dims x 2 rows per thread (uint4 loads) ----
        {
            __half2 a0 = __float2half2_rn(0.f), a1 = a0;
            __half2 b0 = a0, b1 = a0;
            const uint4* cb0 = reinterpret_cast<const uint4*>(&s.combh[0][0]) + chunk * 6;
            const uint4* cb1 = reinterpret_cast<const uint4*>(&s.combh[1][0]) + chunk * 6;
            const uint4* pr  = s.protoP4 + (chunk * 6) * PROTO + pp;
            #pragma unroll
            for (int i = 0; i < 6; i++) {
                uint4 w  = pr[i * PROTO];
                uint4 c0 = cb0[i];
                uint4 c1 = cb1[i];
                a0 = __hfma2(u2h(c0.x), u2h(w.x), a0);
                a1 = __hfma2(u2h(c0.y), u2h(w.y), a1);
                a0 = __hfma2(u2h(c0.z), u2h(w.z), a0);
                a1 = __hfma2(u2h(c0.w), u2h(w.w), a1);
                b0 = __hfma2(u2h(c1.x), u2h(w.x), b0);
                b1 = __hfma2(u2h(c1.y), u2h(w.y), b1);
                b0 = __hfma2(u2h(c1.z), u2h(w.z), b0);
                b1 = __hfma2(u2h(c1.w), u2h(w.w), b1);
            }
            float2 fa0 = __half22float2(a0), fa1 = __half22float2(a1);
            float2 fb0 = __half22float2(b0), fb1 = __half22float2(b1);
            s.part1[chunk][0][pp] = (fa0.x + fa0.y) + (fa1.x + fa1.y);
            s.part1[chunk][1][pp] = (fb0.x + fb0.y) + (fb1.x + fb1.y);
        }
        __syncthreads();   // S1

        // ---- phase 1 combine: k = exp(2*dot - cnorm - pnorm), both rows ----
        if (t < PROTO) {
            float d0 = 0.f, d1 = 0.f;
            #pragma unroll
            for (int c = 0; c < 8; c++) { d0 += s.part1[c][0][t]; d1 += s.part1[c][1][t]; }
            float pn = s.pnorm[t];
            float k0 = __expf(2.f * d0 - s.cn[0] - pn);
            float k1 = __expf(2.f * d1 - s.cn[1] - pn);
            s.kh[t] = __floats2half2_rn(k0, k1);   // (k0, k1)
        }
        __syncthreads();   // S2

        // ---- phase 2 partial: 8 cols x 16 p per thread, uint4 W loads ----
        {
            __half2 A0 = __float2half2_rn(0.f), A1 = A0, A2 = A0, A3 = A0;
            __half2 B0 = A0, B1 = A0, B2 = A0, B3 = A0;
            const int pbase = pg * PPG;
            const __half2* kp = &s.kh[pbase];
            const uint4* wb = (pg == 0)
                ? reinterpret_cast<const uint4*>(s.Wsm) + jo
                : reinterpret_cast<const uint4*>(g_WallT) + (size_t)pbase * 128 + jo;
            #pragma unroll 8
            for (int i = 0; i < PPG; i++) {
                uint4 w = wb[i * 128];
                __half2 k01 = kp[i];
                __half2 klo = __lows2half2(k01, k01);    // (k0,k0)
                __half2 khi = __highs2half2(k01, k01);   // (k1,k1)
                A0 = __hfma2(klo, u2h(w.x), A0);
                A1 = __hfma2(klo, u2h(w.y), A1);
                A2 = __hfma2(klo, u2h(w.z), A2);
                A3 = __hfma2(klo, u2h(w.w), A3);
                B0 = __hfma2(khi, u2h(w.x), B0);
                B1 = __hfma2(khi, u2h(w.y), B1);
                B2 = __hfma2(khi, u2h(w.z), B2);
                B3 = __hfma2(khi, u2h(w.w), B3);
            }
            // store 8 cols as (row0,row1) float2 pairs -> 4x STS.128
            float4* dst = reinterpret_cast<float4*>(&s.part2[pg][j0]);
            float2 r0, r1;
            r0 = __half22float2(A0); r1 = __half22float2(B0);
            dst[0] = make_float4(r0.x, r1.x, r0.y, r1.y);
            r0 = __half22float2(A1); r1 = __half22float2(B1);
            dst[1] = make_float4(r0.x, r1.x, r0.y, r1.y);
            r0 = __half22float2(A2); r1 = __half22float2(B2);
            dst[2] = make_float4(r0.x, r1.x, r0.y, r1.y);
            r0 = __half22float2(A3); r1 = __half22float2(B3);
            dst[3] = make_float4(r0.x, r1.x, r0.y, r1.y);
        }
        __syncthreads();   // S3

        // ---- fused epilogue: gate sums + activations + cell + output ----
        if (t < BC * HID) {
            int b = t >> 8, h = t & 255;
            float z[4];
            #pragma unroll
            for (int g = 0; g < 4; g++) {
                int j = g * 256 + h;
                float acc = s.bsm[j];
                #pragma unroll
                for (int p = 0; p < NPG; p++) {
                    float2 v = s.part2[p][j];
                    acc += b ? v.y : v.x;
                }
                z[g] = acc;
            }
            float fg = fast_sigmoid(z[0]);
            float ig = fast_sigmoid(z[1]);
            float gg = fast_tanh(z[2]);
            float og = fast_sigmoid(z[3]);
            float c  = fmaf(fg, s.csm[b][h], ig * gg);
            s.csm[b][h] = c;
            float hn = og * fast_tanh(c);
            s.comb[b][DIN + h]  = hn;
            s.combh[b][DIN + h] = __float2half(hn);
            int bgl = cta * BC + b;
            out[(size_t)step * BATCH * HID + (size_t)bgl * HID + h] = hn;
            if (step == T_STEPS - 1) {
                size_t base = (size_t)T_STEPS * BATCH * HID;
                out[base + (size_t)bgl * HID + h]                       = hn;
                out[base + (size_t)BATCH * HID + (size_t)bgl * HID + h] = c;
            }
        }
        // wraparound: S0 of next step orders epilogue writes before phase-1 reads
    }
}

extern "C" void kernel_launch(void* const* d_in, const int* in_sizes, int n_in,
                              void* d_out, int out_size) {
    const float* x     = (const float*)d_in[0];
    const float* proto = (const float*)d_in[1];
    const float* Wf    = (const float*)d_in[2];
    const float* bf    = (const float*)d_in[3];
    const float* Wi    = (const float*)d_in[4];
    const float* bi    = (const float*)d_in[5];
    const float* Wg    = (const float*)d_in[6];
    const float* bg    = (const float*)d_in[7];
    const float* Wo    = (const float*)d_in[8];
    const float* bo    = (const float*)d_in[9];
    float* out = (float*)d_out;

    cudaFuncSetAttribute(qlstm_kernel, cudaFuncAttributeMaxDynamicSharedMemorySize,
                         (int)sizeof(Smem));

    prep_kernel<<<128, 256>>>(proto, Wf, Wi, Wg, Wo);
    qlstm_kernel<<<NCTA, NTHREADS, sizeof(Smem)>>>(x, bf, bi, bg, bo, out);
}

// round 12
// speedup vs baseline: 1.1553x; 1.0869x over previous
#include <cuda_runtime.h>
#include <cuda_fp16.h>
#include <cstdint>

// QLSTM: T=512, B=256, D=128, H=256, P=128, GAMMA=1.
// R11: 64 clusters x 2 CTAs x 1024 thr. 4 batch rows per cluster.
// CTA rank owns: proto half (64 p) for phase 1, gate-column half (512 cols,
// W = 128KB SMEM-resident) for phase 2, h half (128 h) for the cell update.
// Cross-CTA per step: k-dup push (1KB) + h push (1KB) via DSMEM; 2 cluster syncs.

#define T_STEPS 512
#define BATCH   256
#define DIN     128
#define HID     256
#define DH      384
#define NTHREADS 1024

__device__ __half g_Whalf[2][128][512];   // [rank][p][j], j = gate*128 + h_local
__device__ uint4  g_protoH[2][48][64];    // [rank][q][pl]: dims 8q..8q+7 (4x half2)
__device__ float  g_pnorm[128];

__global__ void prep_kernel(const float* __restrict__ proto,
                            const float* __restrict__ Wf, const float* __restrict__ Wi,
                            const float* __restrict__ Wg, const float* __restrict__ Wo) {
    int tid = blockIdx.x * blockDim.x + threadIdx.x;
    int nth = gridDim.x * blockDim.x;
    for (int idx = tid; idx < 2 * 128 * 512; idx += nth) {
        int r  = idx >> 16;
        int p  = (idx >> 9) & 127;
        int j  = idx & 511;
        int g  = j >> 7;
        int hl = j & 127;
        const float* W = (g == 0) ? Wf : (g == 1) ? Wi : (g == 2) ? Wg : Wo;
        g_Whalf[r][p][j] = __float2half(W[(r * 128 + hl) * 128 + p]);
    }
    for (int idx = tid; idx < 2 * 48 * 64; idx += nth) {
        int r   = idx / 3072;
        int rem = idx % 3072;
        int q   = rem >> 6;
        int pl  = rem & 63;
        const float* pr = proto + (size_t)(r * 64 + pl) * DH + 8 * q;
        __half2 a = __floats2half2_rn(pr[0], pr[1]);
        __half2 b = __floats2half2_rn(pr[2], pr[3]);
        __half2 c = __floats2half2_rn(pr[4], pr[5]);
        __half2 d = __floats2half2_rn(pr[6], pr[7]);
        uint4 v;
        v.x = *reinterpret_cast<unsigned int*>(&a);
        v.y = *reinterpret_cast<unsigned int*>(&b);
        v.z = *reinterpret_cast<unsigned int*>(&c);
        v.w = *reinterpret_cast<unsigned int*>(&d);
        g_protoH[r][q][pl] = v;
    }
    for (int p = tid; p < 128; p += nth) {
        float s = 0.f;
        for (int d = 0; d < DH; d++) { float v = proto[p * DH + d]; s += v * v; }
        g_pnorm[p] = s;
    }
}

struct Smem {
    __half   Wsm[128 * 512];        // 131072 B  [p][j_own]
    uint4    protoH[48 * 64];       // 49152 B   own proto half
    float2   part1[2][8][64];       // 8192 B    [rowpair][chunk][pl] = (dot_r0, dot_r1)
    unsigned part2[4][4][256];      // 16384 B   [pg][row][colpair] = half2 (c0,c1)
    float    gact[4][512];          // 8192 B    [row][j_own]
    __half   combh[4][DH];          // 3072 B    [row][x | h]
    float    csm[4][128];           // 2048 B    [row][h_local]
    uint4    kdup[128];             // 2048 B    [p_glob] = (k0k0, k1k1, k2k2, k3k3)
    float    bsm[512];              // 2048 B
    float    pnormH[64];            // 256 B
    float    cn[4];                 // 16 B
};                                  // 222480 B

__device__ __forceinline__ float fast_sigmoid(float z) {
    return __fdividef(1.0f, 1.0f + __expf(-z));
}
__device__ __forceinline__ float fast_tanh(float z) {
    float r; asm("tanh.approx.f32 %0, %1;" : "=f"(r) : "f"(z)); return r;
}
__device__ __forceinline__ __half2 u2h(unsigned int v) {
    return *reinterpret_cast<__half2*>(&v);
}
__device__ __forceinline__ unsigned int smem_u32(const void* p) {
    unsigned int a;
    asm("{ .reg .u64 t; cvta.to.shared.u64 t, %1; cvt.u32.u64 %0, t; }" : "=r"(a) : "l"(p));
    return a;
}
#define CLUSTER_SYNC() do { \
    asm volatile("barrier.cluster.arrive.aligned;" ::: "memory"); \
    asm volatile("barrier.cluster.wait.aligned;" ::: "memory"); } while (0)

__global__ __launch_bounds__(NTHREADS, 1)
void qlstm_kernel(const float* __restrict__ x,
                  const float* __restrict__ bf, const float* __restrict__ bi,
                  const float* __restrict__ bg, const float* __restrict__ bo,
                  float* __restrict__ out) {
    extern __shared__ char raw[];
    Smem& s = *reinterpret_cast<Smem*>(raw);

    const int t    = threadIdx.x;
    const int wid  = t >> 5;
    const int lane = t & 31;
    unsigned int rank;
    asm("mov.u32 %0, %%cluster_ctarank;" : "=r"(rank));
    const int cluster = blockIdx.x >> 1;

    // ---- init ----
    {
        const uint4* wsrc = reinterpret_cast<const uint4*>(&g_Whalf[rank][0][0]);
        uint4*       wdst = reinterpret_cast<uint4*>(s.Wsm);
        for (int i = t; i < 131072 / 16; i += NTHREADS) wdst[i] = wsrc[i];
        const uint4* psrc = &g_protoH[rank][0][0];
        for (int i = t; i < 48 * 64; i += NTHREADS) s.protoH[i] = psrc[i];
        for (int j = t; j < 512; j += NTHREADS) {
            int g = j >> 7, hl = j & 127;
            const float* bb = (g == 0) ? bf : (g == 1) ? bi : (g == 2) ? bg : bo;
            s.bsm[j] = bb[rank * 128 + hl];
        }
        for (int i = t; i < 64; i += NTHREADS) s.pnormH[i] = g_pnorm[rank * 64 + i];
        for (int i = t; i < 4 * 128; i += NTHREADS) s.csm[i >> 7][i & 127] = 0.f;
        for (int i = t; i < 4 * HID; i += NTHREADS)
            s.combh[i >> 8][DIN + (i & 255)] = __float2half(0.f);
        if (t < 256) {   // x_0
            int row = t >> 6, i2 = t & 63;
            float2 v = reinterpret_cast<const float2*>(
                x + (size_t)(cluster * 4 + row) * DIN)[i2];
            reinterpret_cast<__half2*>(&s.combh[row][0])[i2] = __floats2half2_rn(v.x, v.y);
        }
    }
    __syncthreads();
    CLUSTER_SYNC();   // peer SMEM init complete before any remote traffic

    unsigned int peer_kdup, peer_combh;
    asm("mapa.shared::cluster.u32 %0, %1, %2;"
        : "=r"(peer_kdup) : "r"(smem_u32(&s.kdup[0])), "r"(rank ^ 1u));
    asm("mapa.shared::cluster.u32 %0, %1, %2;"
        : "=r"(peer_combh) : "r"(smem_u32(&s.combh[0][0])), "r"(rank ^ 1u));

    // phase-1 mapping: rowpair x 8 chunks x 64 pl
    const int rp    = t >> 9;
    const int chunk = (t >> 6) & 7;
    const int pl    = t & 63;
    // phase-2 mapping: 4 p-groups x 256 colpairs
    const int pg    = t >> 8;
    const int cp    = t & 255;

    for (int step = 0; step < T_STEPS; step++) {
        // prefetch x for step+1 (threads 512..767, one (row,i2) each)
        float2 xr = make_float2(0.f, 0.f);
        if (t >= 512 && t < 768 && step + 1 < T_STEPS) {
            int idx = t - 512, row = idx >> 6, i2 = idx & 63;
            xr = reinterpret_cast<const float2*>(
                x + ((size_t)(step + 1) * BATCH + cluster * 4 + row) * DIN)[i2];
        }

        // ---- cnorm (warps 0-3, one row each) ----
        if (wid < 4) {
            float cnv = 0.f;
            const __half2* cb = reinterpret_cast<const __half2*>(&s.combh[wid][0]);
            #pragma unroll
            for (int i = 0; i < 6; i++) {
                float2 v = __half22float2(cb[lane * 6 + i]);
                cnv = fmaf(v.x, v.x, fmaf(v.y, v.y, cnv));
            }
            #pragma unroll
            for (int o = 16; o; o >>= 1) cnv += __shfl_xor_sync(0xffffffffu, cnv, o);
            if (lane == 0) s.cn[wid] = cnv;
        }

        // ---- phase 1: 48 dims x 2 rows (own proto half) ----
        {
            __half2 a0 = __float2half2_rn(0.f), a1 = a0, b0 = a0, b1 = a0;
            const uint4* pr  = s.protoH + (chunk * 6) * 64 + pl;
            const int r0 = 2 * rp;
            const uint4* cb0 = reinterpret_cast<const uint4*>(&s.combh[r0][0])     + chunk * 6;
            const uint4* cb1 = reinterpret_cast<const uint4*>(&s.combh[r0 + 1][0]) + chunk * 6;
            #pragma unroll
            for (int i = 0; i < 6; i++) {
                uint4 w  = pr[i * 64];
                uint4 c0 = cb0[i];
                uint4 c1 = cb1[i];
                a0 = __hfma2(u2h(c0.x), u2h(w.x), a0);
                a1 = __hfma2(u2h(c0.y), u2h(w.y), a1);
                a0 = __hfma2(u2h(c0.z), u2h(w.z), a0);
                a1 = __hfma2(u2h(c0.w), u2h(w.w), a1);
                b0 = __hfma2(u2h(c1.x), u2h(w.x), b0);
                b1 = __hfma2(u2h(c1.y), u2h(w.y), b1);
                b0 = __hfma2(u2h(c1.z), u2h(w.z), b0);
                b1 = __hfma2(u2h(c1.w), u2h(w.w), b1);
            }
            float2 fa0 = __half22float2(a0), fa1 = __half22float2(a1);
            float2 fb0 = __half22float2(b0), fb1 = __half22float2(b1);
            s.part1[rp][chunk][pl] =
                make_float2((fa0.x + fa0.y) + (fa1.x + fa1.y),
                            (fb0.x + fb0.y) + (fb1.x + fb1.y));
        }
        __syncthreads();   // L1

        // ---- k-combine (t<128): own 64 p, 4 rows; push dup-k to peer ----
        if (t < 128) {
            int kp = t & 63, krp = t >> 6;
            float d0 = 0.f, d1 = 0.f;
            #pragma unroll
            for (int c = 0; c < 8; c++) {
                float2 v = s.part1[krp][c][kp];
                d0 += v.x; d1 += v.y;
            }
            float pn = s.pnormH[kp];
            int r0 = 2 * krp;
            float k0 = __expf(2.f * d0 - s.cn[r0]     - pn);
            float k1 = __expf(2.f * d1 - s.cn[r0 + 1] - pn);
            __half2 h0 = __float2half2_rn(k0);       // (k0,k0)
            __half2 h1 = __float2half2_rn(k1);
            unsigned long long pk =
                (unsigned long long)(*reinterpret_cast<unsigned int*>(&h0))
                | ((unsigned long long)(*reinterpret_cast<unsigned int*>(&h1)) << 32);
            int pglob = (int)rank * 64 + kp;
            reinterpret_cast<unsigned long long*>(&s.kdup[pglob])[krp] = pk;
            asm volatile("st.shared::cluster.b64 [%0], %1;"
                         :: "r"(peer_kdup + (unsigned)(pglob * 16 + krp * 8)), "l"(pk)
                         : "memory");
        }
        CLUSTER_SYNC();    // C1: kdup (both halves) visible in both CTAs

        // ---- phase 2: 2 cols x 32 p x 4 rows (own col half, all 128 p) ----
        {
            __half2 A0 = __float2half2_rn(0.f), A1 = A0, A2 = A0, A3 = A0;
            const unsigned int* wb = reinterpret_cast<const unsigned int*>(s.Wsm) + cp;
            const int p0 = pg * 32;
            #pragma unroll 8
            for (int i = 0; i < 32; i++) {
                int p = p0 + i;
                unsigned int w = wb[p * 256];
                uint4 kd = s.kdup[p];
                A0 = __hfma2(u2h(kd.x), u2h(w), A0);
                A1 = __hfma2(u2h(kd.y), u2h(w), A1);
                A2 = __hfma2(u2h(kd.z), u2h(w), A2);
                A3 = __hfma2(u2h(kd.w), u2h(w), A3);
            }
            s.part2[pg][0][cp] = *reinterpret_cast<unsigned int*>(&A0);
            s.part2[pg][1][cp] = *reinterpret_cast<unsigned int*>(&A1);
            s.part2[pg][2][cp] = *reinterpret_cast<unsigned int*>(&A2);
            s.part2[pg][3][cp] = *reinterpret_cast<unsigned int*>(&A3);
        }
        __syncthreads();   // L2

        // ---- psum + activation (all 1024: 256 cp x 4 rows) ----
        {
            int prow = t >> 8, pcp = t & 255;
            float zx = 0.f, zy = 0.f;
            #pragma unroll
            for (int g = 0; g < 4; g++) {
                float2 v = __half22float2(u2h(s.part2[g][prow][pcp]));
                zx += v.x; zy += v.y;
            }
            int c0 = 2 * pcp;
            float z0 = zx + s.bsm[c0];
            float z1 = zy + s.bsm[c0 + 1];
            int gate = c0 >> 7;
            float v0, v1;
            if (gate == 2) { v0 = fast_tanh(z0);    v1 = fast_tanh(z1); }
            else           { v0 = fast_sigmoid(z0); v1 = fast_sigmoid(z1); }
            s.gact[prow][c0]     = v0;
            s.gact[prow][c0 + 1] = v1;
        }
        __syncthreads();   // L3

        // ---- cell update (t<512) + x commit (t in [512,768)) ----
        if (t < 512) {
            int row = t >> 7, hl = t & 127;
            float fg = s.gact[row][hl];
            float ig = s.gact[row][128 + hl];
            float gg = s.gact[row][256 + hl];
            float og = s.gact[row][384 + hl];
            float c  = fmaf(fg, s.csm[row][hl], ig * gg);
            s.csm[row][hl] = c;
            float hn = og * fast_tanh(c);
            int h_glob = (int)rank * 128 + hl;
            int brow   = cluster * 4 + row;
            out[(size_t)step * BATCH * HID + (size_t)brow * HID + h_glob] = hn;
            __half hh = __float2half(hn);
            s.combh[row][DIN + h_glob] = hh;
            asm volatile("st.shared::cluster.b16 [%0], %1;"
                         :: "r"(peer_combh + (unsigned)((row * DH + DIN + h_glob) * 2)),
                            "h"(*reinterpret_cast<unsigned short*>(&hh))
                         : "memory");
            if (step == T_STEPS - 1) {
                size_t base = (size_t)T_STEPS * BATCH * HID;
                out[base + (size_t)brow * HID + h_glob]                       = hn;
                out[base + (size_t)BATCH * HID + (size_t)brow * HID + h_glob] = c;
            }
        } else if (t < 768 && step + 1 < T_STEPS) {
            int idx = t - 512, row = idx >> 6, i2 = idx & 63;
            reinterpret_cast<__half2*>(&s.combh[row][0])[i2] = __floats2half2_rn(xr.x, xr.y);
        }
        CLUSTER_SYNC();    // C2: h pushes + x visible; orders next phase-1 reads
    }
}

extern "C" void kernel_launch(void* const* d_in, const int* in_sizes, int n_in,
                              void* d_out, int out_size) {
    const float* x     = (const float*)d_in[0];
    const float* proto = (const float*)d_in[1];
    const float* Wf    = (const float*)d_in[2];
    const float* bfp   = (const float*)d_in[3];
    const float* Wi    = (const float*)d_in[4];
    const float* bip   = (const float*)d_in[5];
    const float* Wg    = (const float*)d_in[6];
    const float* bgp   = (const float*)d_in[7];
    const float* Wo    = (const float*)d_in[8];
    const float* bop   = (const float*)d_in[9];
    float* out = (float*)d_out;

    cudaFuncSetAttribute(qlstm_kernel, cudaFuncAttributeMaxDynamicSharedMemorySize,
                         (int)sizeof(Smem));

    prep_kernel<<<256, 256>>>(proto, Wf, Wi, Wg, Wo);

    cudaLaunchConfig_t cfg = {};
    cfg.gridDim  = dim3(128, 1, 1);
    cfg.blockDim = dim3(NTHREADS, 1, 1);
    cfg.dynamicSmemBytes = sizeof(Smem);
    cudaLaunchAttribute attrs[1];
    attrs[0].id = cudaLaunchAttributeClusterDimension;
    attrs[0].val.clusterDim.x = 2;
    attrs[0].val.clusterDim.y = 1;
    attrs[0].val.clusterDim.z = 1;
    cfg.attrs = attrs;
    cfg.numAttrs = 1;
    cudaLaunchKernelEx(&cfg, qlstm_kernel, x, bfp, bip, bgp, bop, out);
}